// round 2
// baseline (speedup 1.0000x reference)
#include <cuda_runtime.h>

#define NPTS  2048
#define BATCH 8
#define CINCH 64
#define COUTC 128
#define KNNK  16

// d_out partitioning (float elements)
constexpr size_t OUT2_OFF = (size_t)BATCH * COUTC * NPTS;                     // 2,097,152
constexpr size_t LC_OFF   = OUT2_OFF + (size_t)BATCH * COUTC * NPTS * KNNK;   // 35,651,584

// scratch (no allocations allowed -> device globals)
__device__ float g_sq[BATCH * NPTS];
__device__ int   g_idx[BATCH * NPTS * KNNK];

// ---------- packed fp32x2 helpers ----------
__device__ __forceinline__ unsigned long long pack2(float a, float b) {
    unsigned long long r;
    asm("mov.b64 %0, {%1, %2};" : "=l"(r) : "f"(a), "f"(b));
    return r;
}
__device__ __forceinline__ void unpack2(unsigned long long v, float& a, float& b) {
    asm("mov.b64 {%0, %1}, %2;" : "=f"(a), "=f"(b) : "l"(v));
}
__device__ __forceinline__ void ffma2(unsigned long long& d, unsigned long long a,
                                      unsigned long long b) {
    asm("fma.rn.f32x2 %0, %1, %2, %0;" : "+l"(d) : "l"(a), "l"(b));
}

// ---------- kernel 1: squared norms (exact replication of reference rounding) ----------
// reference: coords*coords (rounded products), then sequential adds, NO fma.
__global__ void sq_kernel(const float* __restrict__ coords) {
    int i = blockIdx.x * blockDim.x + threadIdx.x;  // 0..16383
    int b = i >> 11, n = i & (NPTS - 1);
    const float* cb = coords + (size_t)b * 3 * NPTS;
    float x = cb[n], y = cb[NPTS + n], z = cb[2 * NPTS + n];
    float xx = __fmul_rn(x, x);
    float yy = __fmul_rn(y, y);
    float zz = __fmul_rn(z, z);
    g_sq[i] = __fadd_rn(__fadd_rn(xx, yy), zz);
}

// ---------- kernel 2: KNN (top-16 ascending d2, tie -> smaller index) + local coords ----------
__global__ void __launch_bounds__(256) knn_kernel(const float* __restrict__ coords,
                                                  float* __restrict__ dout) {
    const int bn = blockIdx.x;                 // 0..16383
    const int b = bn >> 11, n = bn & (NPTS - 1);
    const int tid = threadIdx.x;               // 256 threads
    const float* cb = coords + (size_t)b * 3 * NPTS;
    const float qx = cb[n], qy = cb[NPTS + n], qz = cb[2 * NPTS + n];
    const float sqn = g_sq[bn];

    unsigned long long keys[8];
#pragma unroll
    for (int i = 0; i < 8; ++i) {
        int m = tid + (i << 8);
        float mx = cb[m], my = cb[NPTS + m], mz = cb[2 * NPTS + m];
        // reference dot: sgemm K=3 fma chain, k ascending, acc starts at 0
        float dot = fmaf(qz, mz, fmaf(qy, my, __fmul_rn(qx, mx)));
        // reference d2: round(sq_n + sq_m) - round(2*dot), separate ops, no fma
        float t  = __fadd_rn(sqn, g_sq[(b << 11) + m]);
        float d2 = __fsub_rn(t, __fmul_rn(2.0f, dot));
        unsigned u = __float_as_uint(d2);
        u = (u & 0x80000000u) ? ~u : (u | 0x80000000u);   // sortable float bits
        keys[i] = ((unsigned long long)u << 32) | (unsigned)m;
    }

    __shared__ unsigned long long wmin[8];
    __shared__ int sel[KNNK];

    for (int r = 0; r < KNNK; ++r) {
        unsigned long long best = ~0ull;
#pragma unroll
        for (int i = 0; i < 8; ++i) best = (keys[i] < best) ? keys[i] : best;
#pragma unroll
        for (int off = 16; off; off >>= 1) {
            unsigned long long o = __shfl_down_sync(0xffffffffu, best, off);
            best = (o < best) ? o : best;
        }
        if ((tid & 31) == 0) wmin[tid >> 5] = best;
        __syncthreads();
        if (tid == 0) {
            unsigned long long bb = wmin[0];
#pragma unroll
            for (int wi = 1; wi < 8; ++wi) bb = (wmin[wi] < bb) ? wmin[wi] : bb;
            sel[r] = (int)(bb & 0xffffffffull);
        }
        __syncthreads();
        int wm = sel[r];
        if ((wm & 255) == tid) keys[wm >> 8] = ~0ull;   // invalidate winner
    }

    if (tid < KNNK) g_idx[bn * KNNK + tid] = sel[tid];
    if (tid < 3 * KNNK) {
        int c = tid >> 4, k = tid & 15;
        float center = cb[c * NPTS + n];
        float nb = cb[c * NPTS + sel[k]];
        dout[LC_OFF + (((size_t)(b * 3 + c) * NPTS) + n) * KNNK + k] = __fsub_rn(center, nb);
    }
}

// ---------- kernel 3: fused gather -> conv1+BN+ReLU -> conv2+BN+ReLU -> max_k ----------
// Block: 256 threads = 8 warps, one point per warp. SMEM: transposed W1/W2 (shared by
// all warps, conflict-free lane-consecutive reads) + per-warp x-tile and h-tile.
__global__ void __launch_bounds__(256, 1) mlp_kernel(
    const float* __restrict__ x,
    const float* __restrict__ w1, const float* __restrict__ w2,
    const float* __restrict__ g1, const float* __restrict__ b1,
    const float* __restrict__ m1, const float* __restrict__ v1,
    const float* __restrict__ g2, const float* __restrict__ b2,
    const float* __restrict__ m2, const float* __restrict__ v2,
    float* __restrict__ dout) {
    extern __shared__ float smem[];
    float* ws1 = smem;                        // [64][128]  ws1[c*128+o] = w1[o][c]
    float* ws2 = ws1 + CINCH * COUTC;         // [128][128] ws2[c*128+o] = w2[o][c]
    float* xsAll = ws2 + COUTC * COUTC;       // 8 * 1024 floats
    unsigned long long* hsAll =
        (unsigned long long*)(xsAll + 8 * CINCH * KNNK);  // 8 * 1024 u64

    const int tid = threadIdx.x;
    const int w = tid >> 5, lane = tid & 31;

    for (int i = tid; i < CINCH * COUTC; i += 256) {
        int c = i >> 7, o = i & 127;
        ws1[i] = w1[o * CINCH + c];
    }
    for (int i = tid; i < COUTC * COUTC; i += 256) {
        int c = i >> 7, o = i & 127;
        ws2[i] = w2[o * COUTC + c];
    }

    // BN constants for this thread's 4 channels (o = j*32 + lane)
    float s1v[4], c1v[4], s2v[4], c2v[4];
#pragma unroll
    for (int j = 0; j < 4; ++j) {
        int ch = j * 32 + lane;
        float s1 = g1[ch] / sqrtf(v1[ch] + 1e-5f);
        s1v[j] = s1; c1v[j] = b1[ch] - m1[ch] * s1;
        float s2 = g2[ch] / sqrtf(v2[ch] + 1e-5f);
        s2v[j] = s2; c2v[j] = b2[ch] - m2[ch] * s2;
    }
    __syncthreads();

    const int p = blockIdx.x * 8 + w;           // point id 0..16383
    const int b = p >> 11, n = p & (NPTS - 1);
    float* xs = xsAll + w * (CINCH * KNNK);
    unsigned long long* hs = hsAll + w * (COUTC * KNNK / 2);

    // gather neighbors: xs[c*16 + k] = x[b][c][idx[k]]
    {
        const int k = lane & 15;
        const int id = __ldg(&g_idx[p * KNNK + k]);
        const float* xb = x + (size_t)b * CINCH * NPTS;
        for (int c = (lane >> 4); c < CINCH; c += 2)
            xs[c * KNNK + k] = __ldg(&xb[c * NPTS + id]);
    }
    __syncwarp();

    unsigned long long acc[4][8];
#pragma unroll
    for (int j = 0; j < 4; ++j)
#pragma unroll
        for (int q = 0; q < 8; ++q) acc[j][q] = 0ull;

    // GEMM1: h[o][k] = sum_c w1[o][c] * xs[c][k]
    const ulonglong2* xs2 = (const ulonglong2*)xs;
#pragma unroll 4
    for (int c = 0; c < CINCH; ++c) {
        ulonglong2 xv0 = xs2[c * 4 + 0];
        ulonglong2 xv1 = xs2[c * 4 + 1];
        ulonglong2 xv2 = xs2[c * 4 + 2];
        ulonglong2 xv3 = xs2[c * 4 + 3];
        const float* wr = ws1 + c * COUTC + lane;
#pragma unroll
        for (int j = 0; j < 4; ++j) {
            float wv = wr[j * 32];
            unsigned long long wp = pack2(wv, wv);
            ffma2(acc[j][0], wp, xv0.x);
            ffma2(acc[j][1], wp, xv0.y);
            ffma2(acc[j][2], wp, xv1.x);
            ffma2(acc[j][3], wp, xv1.y);
            ffma2(acc[j][4], wp, xv2.x);
            ffma2(acc[j][5], wp, xv2.y);
            ffma2(acc[j][6], wp, xv3.x);
            ffma2(acc[j][7], wp, xv3.y);
        }
    }

    // epilogue 1: BN+ReLU, store h packed as hs[q*128 + ch] (k = 2q, 2q+1)
#pragma unroll
    for (int j = 0; j < 4; ++j) {
        int ch = j * 32 + lane;
#pragma unroll
        for (int q = 0; q < 8; ++q) {
            float lo, hi; unpack2(acc[j][q], lo, hi);
            lo = fmaxf(fmaf(lo, s1v[j], c1v[j]), 0.f);
            hi = fmaxf(fmaf(hi, s1v[j], c1v[j]), 0.f);
            hs[q * COUTC + ch] = pack2(lo, hi);
        }
    }
    __syncwarp();

#pragma unroll
    for (int j = 0; j < 4; ++j)
#pragma unroll
        for (int q = 0; q < 8; ++q) acc[j][q] = 0ull;

    // GEMM2: out[o][k] = sum_c w2[o][c] * h[c][k]
#pragma unroll 4
    for (int c = 0; c < COUTC; ++c) {
        unsigned long long hv[8];
#pragma unroll
        for (int q = 0; q < 8; ++q) hv[q] = hs[q * COUTC + c];
        const float* wr = ws2 + c * COUTC + lane;
#pragma unroll
        for (int j = 0; j < 4; ++j) {
            float wv = wr[j * 32];
            unsigned long long wp = pack2(wv, wv);
#pragma unroll
            for (int q = 0; q < 8; ++q) ffma2(acc[j][q], wp, hv[q]);
        }
    }

    // epilogue 2: BN+ReLU, write knn_mlp_x and y (max over k; ReLU => max >= 0)
    float* out2 = dout + OUT2_OFF;
#pragma unroll
    for (int j = 0; j < 4; ++j) {
        int ch = j * 32 + lane;
        float vals[16];
        float mx = 0.f;
#pragma unroll
        for (int q = 0; q < 8; ++q) {
            float lo, hi; unpack2(acc[j][q], lo, hi);
            lo = fmaxf(fmaf(lo, s2v[j], c2v[j]), 0.f);
            hi = fmaxf(fmaf(hi, s2v[j], c2v[j]), 0.f);
            mx = fmaxf(mx, fmaxf(lo, hi));
            vals[2 * q] = lo; vals[2 * q + 1] = hi;
        }
        float4* o4 = (float4*)(out2 + (((size_t)(b * COUTC + ch)) * NPTS + n) * KNNK);
        o4[0] = make_float4(vals[0], vals[1], vals[2], vals[3]);
        o4[1] = make_float4(vals[4], vals[5], vals[6], vals[7]);
        o4[2] = make_float4(vals[8], vals[9], vals[10], vals[11]);
        o4[3] = make_float4(vals[12], vals[13], vals[14], vals[15]);
        dout[(size_t)(b * COUTC + ch) * NPTS + n] = mx;
    }
}

extern "C" void kernel_launch(void* const* d_in, const int* in_sizes, int n_in,
                              void* d_out, int out_size) {
    const float* x      = (const float*)d_in[0];
    const float* coords = (const float*)d_in[1];
    const float* w1     = (const float*)d_in[2];
    const float* g1     = (const float*)d_in[3];
    const float* b1     = (const float*)d_in[4];
    const float* m1     = (const float*)d_in[5];
    const float* v1     = (const float*)d_in[6];
    const float* w2     = (const float*)d_in[7];
    const float* g2     = (const float*)d_in[8];
    const float* b2     = (const float*)d_in[9];
    const float* m2     = (const float*)d_in[10];
    const float* v2     = (const float*)d_in[11];
    float* out = (float*)d_out;

    sq_kernel<<<(BATCH * NPTS) / 256, 256>>>(coords);
    knn_kernel<<<BATCH * NPTS, 256>>>(coords, out);

    const int smem_bytes = (CINCH * COUTC + COUTC * COUTC + 8 * CINCH * KNNK) * 4
                         + 8 * (COUTC * KNNK / 2) * 8;   // 196608 = 192 KB
    cudaFuncSetAttribute(mlp_kernel, cudaFuncAttributeMaxDynamicSharedMemorySize, smem_bytes);
    mlp_kernel<<<(BATCH * NPTS) / 8, 256, smem_bytes>>>(
        x, w1, w2, g1, b1, m1, v1, g2, b2, m2, v2, out);
}